// round 12
// baseline (speedup 1.0000x reference)
#include <cuda_runtime.h>
#include <math.h>

// Problem constants (fixed by reference)
#define T_STEPS 128
#define MATPTS  16
#define PPT     2                    // material points per thread (1 packed pair)
#define TPB     (MATPTS / PPT)       // threads per batch element = 8
#define BLOCK   128

// Material constants, derived in double precision at compile time
static constexpr double E_MOD_D = 3130.0;
static constexpr double NU_D    = 0.37;
static constexpr double MU_D    = E_MOD_D / (2.0 * (1.0 + NU_D));
static constexpr double LAM_D   = E_MOD_D * NU_D / ((1.0 + NU_D) * (1.0 - 2.0 * NU_D));
static constexpr double SIGY_D  = 64.8;
static constexpr double H_D     = 300.0;
static constexpr double KINV_D  = 1.0 / (3.0 * MU_D + H_D);
static constexpr double SQRT3_D = 1.7320508075688772;

static constexpr float TWO_MU_F = (float)(2.0 * MU_D);
static constexpr float K3_F     = (float)(LAM_D + 2.0 * MU_D / 3.0);  // pm = K3*(e0+e1)
static constexpr float NC23_F   = (float)(-2.0 * MU_D / 3.0);         // deviator correction
static constexpr float KS3_F    = (float)(SQRT3_D * KINV_D);          // Kinv*sqrt(3)
static constexpr float NHK_F    = (float)(-H_D * KINV_D);             // -H*Kinv
static constexpr float NYS0_F   = (float)(-SIGY_D * KINV_D);          // initial yield state
static constexpr float N15S3_F  = (float)(-1.5 / SQRT3_D);            // -1.5/sqrt(3)

// ---- packed fp32x2 helpers (sm_100+ only) ---------------------------------
// Only fma.rn/add.rn/mul.rn exist in the f32x2 PTX family.
typedef unsigned long long u64t;
struct F2 { u64t v; };

__device__ __forceinline__ F2 f2pack(float lo, float hi) {
    F2 r; asm("mov.b64 %0, {%1, %2};" : "=l"(r.v) : "f"(lo), "f"(hi)); return r;
}
__device__ __forceinline__ void f2unpack(F2 a, float& lo, float& hi) {
    asm("mov.b64 {%0, %1}, %2;" : "=f"(lo), "=f"(hi) : "l"(a.v));
}
__device__ __forceinline__ F2 f2fma(F2 a, F2 b, F2 c) {
    F2 r; asm("fma.rn.f32x2 %0, %1, %2, %3;" : "=l"(r.v) : "l"(a.v), "l"(b.v), "l"(c.v)); return r;
}
__device__ __forceinline__ F2 f2add(F2 a, F2 b) {
    F2 r; asm("add.rn.f32x2 %0, %1, %2;" : "=l"(r.v) : "l"(a.v), "l"(b.v)); return r;
}
__device__ __forceinline__ F2 f2mul(F2 a, F2 b) {
    F2 r; asm("mul.rn.f32x2 %0, %1, %2;" : "=l"(r.v) : "l"(a.v), "l"(b.v)); return r;
}
// relu on both packed halves (scalar fmaxf with immediate 0)
__device__ __forceinline__ F2 f2relu(F2 a) {
    float lo, hi; f2unpack(a, lo, hi);
    return f2pack(fmaxf(lo, 0.0f), fmaxf(hi, 0.0f));
}
__device__ __forceinline__ F2 f2zero() { F2 r; r.v = 0ULL; return r; }

__global__ void __launch_bounds__(BLOCK, 7)
prnn_j2_kernel(const float* __restrict__ x,
               const float* __restrict__ W1,
               const float* __restrict__ W2,
               float* __restrict__ out,
               int B)
{
    const int tid = blockIdx.x * BLOCK + threadIdx.x;
    const int b   = tid >> 3;           // batch element
    const int sub = tid & 7;            // sub-lane within the 8-thread group
    if (b >= B) return;

    // loop-invariant predicates / routing for the transpose-reduction
    const bool lo4 = (sub < 4);
    const bool lo2 = (sub < 2);
    const bool mid = (sub < 4) && (sub >= 2);
    const bool r2sel = ((sub & 2) != 0);
    const bool do_store = ((sub & 1) == 0) && (sub < 6);
    const int  comp = sub >> 1;

    // ---- Packed per-thread weight slices --------------------------------
    // W1 row 2 (shear) pre-scaled by 0.5 so eexy = e2' + npxy (no HALF const).
    const int mlo = sub * PPT;
    F2 w1p[3][3];
    F2 w2p[3][3];
    #pragma unroll
    for (int j = 0; j < 3; ++j) {
        const float sc = (j == 2) ? 0.5f : 1.0f;
        #pragma unroll
        for (int f = 0; f < 3; ++f)
            w1p[j][f] = f2pack(sc * __ldg(&W1[(3 * mlo + j) * 3 + f]),
                               sc * __ldg(&W1[(3 * (mlo + 1) + j) * 3 + f]));
    }
    #pragma unroll
    for (int o = 0; o < 3; ++o)
        #pragma unroll
        for (int j = 0; j < 3; ++j) {
            float wl = __ldg(&W2[o * 48 + 3 * mlo + j]);
            float wh = __ldg(&W2[o * 48 + 3 * (mlo + 1) + j]);
            w2p[o][j] = f2pack(log1pf(expf(wl)), log1pf(expf(wh)));
        }

    // ---- Packed constants (7 F2 = 14 regs) --------------------------------
    const F2 TWOMU2 = f2pack(TWO_MU_F, TWO_MU_F);
    const F2 K32    = f2pack(K3_F,     K3_F);
    const F2 NC232  = f2pack(NC23_F,   NC23_F);
    const F2 KS32   = f2pack(KS3_F,    KS3_F);
    const F2 NHK2   = f2pack(NHK_F,    NHK_F);
    const F2 N15S32 = f2pack(N15S3_F,  N15S3_F);
    const F2 ONE2   = f2pack(1.0f,     1.0f);

    // ---- Committed history (negated plastic strain; folded yield state) --
    F2 npxx = f2zero(), npyy = f2zero(), npxy = f2zero();
    F2 nysK = f2pack(NYS0_F, NYS0_F);   // Kinv*(-sigy - H*alpha)

    const float2* xq = (const float2*)(x + (size_t)b * (T_STEPS * 3));
    float*        opc = out + (size_t)b * (T_STEPS * 3) + comp;

    // one step: J2 update + fc2 + transpose-reduction + store
    auto step = [&](float ex, float ey, float eg, float* dst) {
        const F2 ex2 = f2pack(ex, ex);
        const F2 ey2 = f2pack(ey, ey);
        const F2 eg2 = f2pack(eg, eg);

        // fc1: per-point strain (row 2 pre-scaled by 0.5)
        const F2 e0 = f2fma(ex2, w1p[0][0], f2fma(ey2, w1p[0][1], f2mul(eg2, w1p[0][2])));
        const F2 e1 = f2fma(ex2, w1p[1][0], f2fma(ey2, w1p[1][1], f2mul(eg2, w1p[1][2])));
        const F2 e2 = f2fma(ex2, w1p[2][0], f2fma(ey2, w1p[2][1], f2mul(eg2, w1p[2][2])));

        // elastic predictor, deviatoric form (state negated)
        const F2 eexx = f2add(e0, npxx);
        const F2 eeyy = f2add(e1, npyy);
        const F2 eexy = f2add(e2, npxy);
        const F2 t01  = f2add(e0, e1);
        const F2 pm   = f2mul(K32,  t01);
        const F2 nctr = f2mul(NC232, t01);
        const F2 dxx  = f2fma(TWOMU2, eexx, nctr);
        const F2 dyy  = f2fma(TWOMU2, eeyy, nctr);
        const F2 sxy  = f2mul(TWOMU2, eexy);

        // u = dxx^2 + dxx*dyy + dyy^2 + sxy^2  (q^2 = 3u), tree form
        const F2 sd  = f2add(dxx, dyy);
        const F2 A   = f2mul(sxy, sxy);
        const F2 p1  = f2mul(dxx, sd);
        const F2 p2  = f2fma(dyy, dyy, A);
        const F2 u2  = f2add(p1, p2);

        // radial return (sqrt(3) and Kinv folded into constants)
        float u_lo, u_hi;
        f2unpack(u2, u_lo, u_hi);
        u_lo = fmaxf(u_lo, 1e-24f);
        u_hi = fmaxf(u_hi, 1e-24f);
        const F2 r2p = f2pack(rsqrtf(u_lo), rsqrtf(u_hi));
        const F2 nr2 = f2mul(N15S32, r2p);         // -1.5/(sqrt(3)q-scale), off chain
        const F2 ur2 = f2mul(u2, r2p);             // sqrt(u) = q/sqrt(3)
        const F2 fk2 = f2fma(KS32, ur2, nysK);     // Kinv*(q - sigy - H*alpha)
        const F2 dg2 = f2relu(fk2);                // dgam
        nysK = f2fma(NHK2, dg2, nysK);             // alpha += dg (folded)
        const F2 nc2 = f2mul(dg2, nr2);            // -1.5*dgam/q

        // commit plastic strain
        npxx = f2fma(nc2, dxx, npxx);
        npyy = f2fma(nc2, dyy, npyy);
        npxy = f2fma(nc2, sxy, npxy);

        // corrected stress: o = d*(1 + 2mu*nc) + pm
        const F2 wf  = f2fma(TWOMU2, nc2, ONE2);
        const F2 oxx = f2fma(dxx, wf, pm);
        const F2 oyy = f2fma(dyy, wf, pm);
        const F2 oxy = f2mul(sxy, wf);

        // fc2 partial (softplus weights)
        const F2 a0 = f2fma(oxx, w2p[0][0], f2fma(oyy, w2p[0][1], f2mul(oxy, w2p[0][2])));
        const F2 a1 = f2fma(oxx, w2p[1][0], f2fma(oyy, w2p[1][1], f2mul(oxy, w2p[1][2])));
        const F2 a2 = f2fma(oxx, w2p[2][0], f2fma(oyy, w2p[2][1], f2mul(oxy, w2p[2][2])));

        // collapse packed pair slots
        float a0l, a0h, a1l, a1h, a2l, a2h;
        f2unpack(a0, a0l, a0h);
        f2unpack(a1, a1l, a1h);
        f2unpack(a2, a2l, a2h);
        float r0 = a0l + a0h, r1 = a1l + a1h, r2 = a2l + a2h;

        // transpose-reduction over the 8-lane group: 4 SHFL total
        float v1 = lo4 ? r2 : r0;
        float w1 = __shfl_xor_sync(0xffffffffu, v1, 4);
        if (lo4) r0 += w1; else r2 += w1;
        float w2 = __shfl_xor_sync(0xffffffffu, r1, 4);
        if (lo4) r1 += w2;
        float v3 = lo4 ? (r2sel ? r0 : r1) : r2;
        float w3 = __shfl_xor_sync(0xffffffffu, v3, 2);
        if (lo2)      r0 += w3;
        else if (mid) r1 += w3;
        else          r2 += w3;
        float v4 = lo2 ? r0 : (lo4 ? r1 : r2);
        float w4 = __shfl_xor_sync(0xffffffffu, v4, 1);
        const float total = v4 + w4;

        if (do_store) *dst = total;
    };

    // software-pipelined pair loads (3 x LDG.64 per 2 steps)
    float2 cA = xq[0], cB = xq[1], cC = xq[2];

    #pragma unroll 1
    for (int k = 0; k < T_STEPS / 2; ++k) {
        // clamped prefetch of the next pair (no branch)
        const float2* nq = xq + ((k + 1 < T_STEPS / 2) ? 3 : 0);
        const float2 nA = nq[0], nB = nq[1], nC = nq[2];

        // step 2k: (f0, f1, f2)   step 2k+1: (f3, f4, f5)
        step(cA.x, cA.y, cB.x, opc);
        step(cB.y, cC.x, cC.y, opc + 3);

        cA = nA; cB = nB; cC = nC;
        xq += 3;
        opc += 6;
    }
}

extern "C" void kernel_launch(void* const* d_in, const int* in_sizes, int n_in,
                              void* d_out, int out_size)
{
    const float* x  = (const float*)d_in[0];   // [B, T, 3]
    const float* W1 = (const float*)d_in[1];   // [48, 3]
    const float* W2 = (const float*)d_in[2];   // [3, 48]
    float* out      = (float*)d_out;           // [B, T, 3]

    const int B = in_sizes[0] / (T_STEPS * 3);
    const int total_threads = B * TPB;
    const int grid = (total_threads + BLOCK - 1) / BLOCK;

    prnn_j2_kernel<<<grid, BLOCK>>>(x, W1, W2, out, B);
}

// round 13
// speedup vs baseline: 1.0058x; 1.0058x over previous
#include <cuda_runtime.h>
#include <math.h>

// Problem constants (fixed by reference)
#define T_STEPS 128
#define MATPTS  16
#define PPT     2                    // material points per thread (1 packed pair)
#define TPB     (MATPTS / PPT)       // threads per batch element = 8
#define BLOCK   128
#define CHUNK   16                   // timesteps staged in SMEM per phase
#define NCHUNK  (T_STEPS / CHUNK)    // 8
#define GRP     (BLOCK / TPB)        // 16 batch elements per block

// Material constants, derived in double precision at compile time
static constexpr double E_MOD_D = 3130.0;
static constexpr double NU_D    = 0.37;
static constexpr double MU_D    = E_MOD_D / (2.0 * (1.0 + NU_D));
static constexpr double LAM_D   = E_MOD_D * NU_D / ((1.0 + NU_D) * (1.0 - 2.0 * NU_D));
static constexpr double SIGY_D  = 64.8;
static constexpr double H_D     = 300.0;
static constexpr double KINV_D  = 1.0 / (3.0 * MU_D + H_D);
static constexpr double SQRT3_D = 1.7320508075688772;

static constexpr float TWO_MU_F = (float)(2.0 * MU_D);
static constexpr float K3_F     = (float)(LAM_D + 2.0 * MU_D / 3.0);  // pm = K3*(e0+e1)
static constexpr float NC23_F   = (float)(-2.0 * MU_D / 3.0);         // deviator correction
static constexpr float KS3_F    = (float)(SQRT3_D * KINV_D);          // Kinv*sqrt(3)
static constexpr float NHK_F    = (float)(-H_D * KINV_D);             // -H*Kinv
static constexpr float NYS0_F   = (float)(-SIGY_D * KINV_D);          // initial yield state
static constexpr float N15S3_F  = (float)(-1.5 / SQRT3_D);            // -1.5/sqrt(3)

// ---- packed fp32x2 helpers (sm_100+ only) ---------------------------------
typedef unsigned long long u64t;
struct F2 { u64t v; };

__device__ __forceinline__ F2 f2pack(float lo, float hi) {
    F2 r; asm("mov.b64 %0, {%1, %2};" : "=l"(r.v) : "f"(lo), "f"(hi)); return r;
}
__device__ __forceinline__ void f2unpack(F2 a, float& lo, float& hi) {
    asm("mov.b64 {%0, %1}, %2;" : "=f"(lo), "=f"(hi) : "l"(a.v));
}
__device__ __forceinline__ F2 f2fma(F2 a, F2 b, F2 c) {
    F2 r; asm("fma.rn.f32x2 %0, %1, %2, %3;" : "=l"(r.v) : "l"(a.v), "l"(b.v), "l"(c.v)); return r;
}
__device__ __forceinline__ F2 f2add(F2 a, F2 b) {
    F2 r; asm("add.rn.f32x2 %0, %1, %2;" : "=l"(r.v) : "l"(a.v), "l"(b.v)); return r;
}
__device__ __forceinline__ F2 f2mul(F2 a, F2 b) {
    F2 r; asm("mul.rn.f32x2 %0, %1, %2;" : "=l"(r.v) : "l"(a.v), "l"(b.v)); return r;
}
__device__ __forceinline__ F2 f2relu(F2 a) {
    float lo, hi; f2unpack(a, lo, hi);
    return f2pack(fmaxf(lo, 0.0f), fmaxf(hi, 0.0f));
}
__device__ __forceinline__ F2 f2zero() { F2 r; r.v = 0ULL; return r; }

__global__ void __launch_bounds__(BLOCK, 7)
prnn_j2_kernel(const float* __restrict__ x,
               const float* __restrict__ W1,
               const float* __restrict__ W2,
               float* __restrict__ out,
               int B)
{
    __shared__ float sbuf[3][CHUNK][BLOCK];   // 24 KB

    const int tid = threadIdx.x;
    const int b   = blockIdx.x * GRP + (tid >> 3);   // batch element
    const int sub = tid & 7;
    const int bc  = (b < B) ? b : (B - 1);            // clamp for safety (keeps barriers uniform)

    // ---- Packed per-thread weight slices --------------------------------
    // W1 row 2 (shear) pre-scaled by 0.5.
    const int mlo = sub * PPT;
    F2 w1p[3][3];
    F2 w2p[3][3];
    #pragma unroll
    for (int j = 0; j < 3; ++j) {
        const float sc = (j == 2) ? 0.5f : 1.0f;
        #pragma unroll
        for (int f = 0; f < 3; ++f)
            w1p[j][f] = f2pack(sc * __ldg(&W1[(3 * mlo + j) * 3 + f]),
                               sc * __ldg(&W1[(3 * (mlo + 1) + j) * 3 + f]));
    }
    #pragma unroll
    for (int o = 0; o < 3; ++o)
        #pragma unroll
        for (int j = 0; j < 3; ++j) {
            float wl = __ldg(&W2[o * 48 + 3 * mlo + j]);
            float wh = __ldg(&W2[o * 48 + 3 * (mlo + 1) + j]);
            w2p[o][j] = f2pack(log1pf(expf(wl)), log1pf(expf(wh)));
        }

    // ---- Packed constants --------------------------------------------------
    const F2 TWOMU2 = f2pack(TWO_MU_F, TWO_MU_F);
    const F2 K32    = f2pack(K3_F,     K3_F);
    const F2 NC232  = f2pack(NC23_F,   NC23_F);
    const F2 KS32   = f2pack(KS3_F,    KS3_F);
    const F2 NHK2   = f2pack(NHK_F,    NHK_F);
    const F2 N15S32 = f2pack(N15S3_F,  N15S3_F);
    const F2 ONE2   = f2pack(1.0f,     1.0f);
    const F2 TINY2  = f2pack(1e-24f,   1e-24f);

    // ---- Committed history (negated plastic strain; folded yield state) --
    F2 npxx = f2zero(), npyy = f2zero(), npxy = f2zero();
    F2 nysK = f2pack(NYS0_F, NYS0_F);   // Kinv*(-sigy - H*alpha)

    const float2* xq = (const float2*)(x + (size_t)bc * (T_STEPS * 3));
    const int bbase = blockIdx.x * GRP;

    // one step: J2 update + fc2 partial -> SMEM (no reduction on the chain)
    auto step = [&](float ex, float ey, float eg, int tloc) {
        const F2 ex2 = f2pack(ex, ex);
        const F2 ey2 = f2pack(ey, ey);
        const F2 eg2 = f2pack(eg, eg);

        // fc1: per-point strain (row 2 pre-scaled by 0.5)
        const F2 e0 = f2fma(ex2, w1p[0][0], f2fma(ey2, w1p[0][1], f2mul(eg2, w1p[0][2])));
        const F2 e1 = f2fma(ex2, w1p[1][0], f2fma(ey2, w1p[1][1], f2mul(eg2, w1p[1][2])));
        const F2 e2 = f2fma(ex2, w1p[2][0], f2fma(ey2, w1p[2][1], f2mul(eg2, w1p[2][2])));

        // elastic predictor, deviatoric form (state negated)
        const F2 eexx = f2add(e0, npxx);
        const F2 eeyy = f2add(e1, npyy);
        const F2 eexy = f2add(e2, npxy);
        const F2 t01  = f2add(e0, e1);
        const F2 pm   = f2mul(K32,  t01);
        const F2 nctr = f2mul(NC232, t01);
        const F2 dxx  = f2fma(TWOMU2, eexx, nctr);
        const F2 dyy  = f2fma(TWOMU2, eeyy, nctr);
        const F2 sxy  = f2mul(TWOMU2, eexy);

        // u = dxx^2 + dxx*dyy + dyy^2 + sxy^2  (q^2 = 3u); TINY seed guards u=0
        const F2 sd  = f2add(dxx, dyy);
        const F2 A   = f2fma(sxy, sxy, TINY2);
        const F2 p1  = f2mul(dxx, sd);
        const F2 p2  = f2fma(dyy, dyy, A);
        const F2 u2  = f2add(p1, p2);

        // radial return (sqrt(3), Kinv folded); only rsqrt is scalar
        float u_lo, u_hi;
        f2unpack(u2, u_lo, u_hi);
        const F2 r2p = f2pack(rsqrtf(u_lo), rsqrtf(u_hi));
        const F2 nr2 = f2mul(N15S32, r2p);
        const F2 ur2 = f2mul(u2, r2p);             // sqrt(u) = q/sqrt(3)
        const F2 fk2 = f2fma(KS32, ur2, nysK);     // Kinv*(q - sigy - H*alpha)
        const F2 dg2 = f2relu(fk2);
        nysK = f2fma(NHK2, dg2, nysK);
        const F2 nc2 = f2mul(dg2, nr2);            // -1.5*dgam/q

        // commit plastic strain
        npxx = f2fma(nc2, dxx, npxx);
        npyy = f2fma(nc2, dyy, npyy);
        npxy = f2fma(nc2, sxy, npxy);

        // corrected stress: o = d*(1 + 2mu*nc) + pm
        const F2 wf  = f2fma(TWOMU2, nc2, ONE2);
        const F2 oxx = f2fma(dxx, wf, pm);
        const F2 oyy = f2fma(dyy, wf, pm);
        const F2 oxy = f2mul(sxy, wf);

        // fc2 partial (softplus weights)
        const F2 a0 = f2fma(oxx, w2p[0][0], f2fma(oyy, w2p[0][1], f2mul(oxy, w2p[0][2])));
        const F2 a1 = f2fma(oxx, w2p[1][0], f2fma(oyy, w2p[1][1], f2mul(oxy, w2p[1][2])));
        const F2 a2 = f2fma(oxx, w2p[2][0], f2fma(oyy, w2p[2][1], f2mul(oxy, w2p[2][2])));

        // collapse packed pair slots -> 3 coalesced STS (fire-and-forget)
        float a0l, a0h, a1l, a1h, a2l, a2h;
        f2unpack(a0, a0l, a0h);
        f2unpack(a1, a1l, a1h);
        f2unpack(a2, a2l, a2h);
        sbuf[0][tloc][tid] = a0l + a0h;
        sbuf[1][tloc][tid] = a1l + a1h;
        sbuf[2][tloc][tid] = a2l + a2h;
    };

    #pragma unroll 1
    for (int chunk = 0; chunk < NCHUNK; ++chunk) {
        // ---- phase 1: CHUNK timesteps of J2 recurrence ----
        #pragma unroll 2
        for (int k = 0; k < CHUNK / 2; ++k) {
            const float2 cA = xq[0], cB = xq[1], cC = xq[2];
            step(cA.x, cA.y, cB.x, 2 * k);
            step(cB.y, cC.x, cC.y, 2 * k + 1);
            xq += 3;
        }
        __syncthreads();

        // ---- phase 2: bulk reduction, 6 outputs per thread ----
        #pragma unroll
        for (int i = 0; i < 6; ++i) {
            const int m = tid * 2 + (i >= 3 ? 1 : 0);   // 0..255
            const int g = m & 15;                        // batch group in block
            const int t = m >> 4;                        // timestep in chunk
            const int c = (i >= 3) ? (i - 3) : i;        // component
            const float4* p = (const float4*)&sbuf[c][t][g * 8];
            const float4 A = p[0], Bv = p[1];
            const float s = ((A.x + A.y) + (A.z + A.w)) + ((Bv.x + Bv.y) + (Bv.z + Bv.w));
            const int gb = bbase + g;
            if (gb < B)
                out[(size_t)gb * (T_STEPS * 3) + (chunk * CHUNK + t) * 3 + c] = s;
        }
        __syncthreads();
    }
}

extern "C" void kernel_launch(void* const* d_in, const int* in_sizes, int n_in,
                              void* d_out, int out_size)
{
    const float* x  = (const float*)d_in[0];   // [B, T, 3]
    const float* W1 = (const float*)d_in[1];   // [48, 3]
    const float* W2 = (const float*)d_in[2];   // [3, 48]
    float* out      = (float*)d_out;           // [B, T, 3]

    const int B = in_sizes[0] / (T_STEPS * 3);
    const int grid = (B + GRP - 1) / GRP;      // 16 batch elements per block

    prnn_j2_kernel<<<grid, BLOCK>>>(x, W1, W2, out, B);
}

// round 14
// speedup vs baseline: 1.0273x; 1.0214x over previous
#include <cuda_runtime.h>
#include <math.h>

// Problem constants (fixed by reference)
#define T_STEPS 128
#define MATPTS  16
#define PPT     2                    // material points per thread (1 packed pair)
#define TPB     (MATPTS / PPT)       // threads per batch element = 8
#define BLOCK   128

// Material constants, derived in double precision at compile time
static constexpr double E_MOD_D = 3130.0;
static constexpr double NU_D    = 0.37;
static constexpr double MU_D    = E_MOD_D / (2.0 * (1.0 + NU_D));
static constexpr double LAM_D   = E_MOD_D * NU_D / ((1.0 + NU_D) * (1.0 - 2.0 * NU_D));
static constexpr double SIGY_D  = 64.8;
static constexpr double H_D     = 300.0;
static constexpr double KINV_D  = 1.0 / (3.0 * MU_D + H_D);
static constexpr double SQRT3_D = 1.7320508075688772;

static constexpr float TWO_MU_F = (float)(2.0 * MU_D);
static constexpr float K3_F     = (float)(LAM_D + 2.0 * MU_D / 3.0);  // pm = K3*(e0+e1)
static constexpr float NC23_F   = (float)(-2.0 * MU_D / 3.0);         // deviator correction
static constexpr float KS3_F    = (float)(SQRT3_D * KINV_D);          // Kinv*sqrt(3)
static constexpr float NHK_F    = (float)(-H_D * KINV_D);             // -H*Kinv
static constexpr float NYS0_F   = (float)(-SIGY_D * KINV_D);          // initial yield state
static constexpr float N15S3_F  = (float)(-1.5 / SQRT3_D);            // -1.5/sqrt(3)

// ---- packed fp32x2 helpers (sm_100+ only) ---------------------------------
typedef unsigned long long u64t;
struct F2 { u64t v; };

__device__ __forceinline__ F2 f2pack(float lo, float hi) {
    F2 r; asm("mov.b64 %0, {%1, %2};" : "=l"(r.v) : "f"(lo), "f"(hi)); return r;
}
__device__ __forceinline__ void f2unpack(F2 a, float& lo, float& hi) {
    asm("mov.b64 {%0, %1}, %2;" : "=f"(lo), "=f"(hi) : "l"(a.v));
}
__device__ __forceinline__ F2 f2fma(F2 a, F2 b, F2 c) {
    F2 r; asm("fma.rn.f32x2 %0, %1, %2, %3;" : "=l"(r.v) : "l"(a.v), "l"(b.v), "l"(c.v)); return r;
}
__device__ __forceinline__ F2 f2add(F2 a, F2 b) {
    F2 r; asm("add.rn.f32x2 %0, %1, %2;" : "=l"(r.v) : "l"(a.v), "l"(b.v)); return r;
}
__device__ __forceinline__ F2 f2mul(F2 a, F2 b) {
    F2 r; asm("mul.rn.f32x2 %0, %1, %2;" : "=l"(r.v) : "l"(a.v), "l"(b.v)); return r;
}
__device__ __forceinline__ F2 f2relu(F2 a) {
    float lo, hi; f2unpack(a, lo, hi);
    return f2pack(fmaxf(lo, 0.0f), fmaxf(hi, 0.0f));
}
__device__ __forceinline__ F2 f2zero() { F2 r; r.v = 0ULL; return r; }

__global__ void __launch_bounds__(BLOCK, 6)
prnn_j2_kernel(const float* __restrict__ x,
               const float* __restrict__ W1,
               const float* __restrict__ W2,
               float* __restrict__ out,
               int B)
{
    const int tid = blockIdx.x * BLOCK + threadIdx.x;
    const int b   = tid >> 3;           // batch element
    const int sub = tid & 7;            // sub-lane within the 8-thread group
    if (b >= B) return;

    // loop-invariant predicates / routing for the transpose-reduction
    const bool lo4 = (sub < 4);
    const bool lo2 = (sub < 2);
    const bool mid = (sub < 4) && (sub >= 2);
    const bool r2sel = ((sub & 2) != 0);
    const bool do_store = ((sub & 1) == 0) && (sub < 6);
    const int  comp = sub >> 1;

    // ---- Packed per-thread weight slices --------------------------------
    // W1 row 2 (shear) pre-scaled by 0.5 so eexy = e2' + npxy.
    const int mlo = sub * PPT;
    F2 w1p[3][3];
    F2 w2p[3][3];
    #pragma unroll
    for (int j = 0; j < 3; ++j) {
        const float sc = (j == 2) ? 0.5f : 1.0f;
        #pragma unroll
        for (int f = 0; f < 3; ++f)
            w1p[j][f] = f2pack(sc * __ldg(&W1[(3 * mlo + j) * 3 + f]),
                               sc * __ldg(&W1[(3 * (mlo + 1) + j) * 3 + f]));
    }
    #pragma unroll
    for (int o = 0; o < 3; ++o)
        #pragma unroll
        for (int j = 0; j < 3; ++j) {
            float wl = __ldg(&W2[o * 48 + 3 * mlo + j]);
            float wh = __ldg(&W2[o * 48 + 3 * (mlo + 1) + j]);
            w2p[o][j] = f2pack(log1pf(expf(wl)), log1pf(expf(wh)));
        }

    // ---- Packed constants --------------------------------------------------
    const F2 TWOMU2 = f2pack(TWO_MU_F, TWO_MU_F);
    const F2 K32    = f2pack(K3_F,     K3_F);
    const F2 NC232  = f2pack(NC23_F,   NC23_F);
    const F2 KS32   = f2pack(KS3_F,    KS3_F);
    const F2 NHK2   = f2pack(NHK_F,    NHK_F);
    const F2 N15S32 = f2pack(N15S3_F,  N15S3_F);
    const F2 ONE2   = f2pack(1.0f,     1.0f);
    const F2 TINY2  = f2pack(1e-24f,   1e-24f);

    // ---- Committed history (negated plastic strain; folded yield state) --
    F2 npxx = f2zero(), npyy = f2zero(), npxy = f2zero();
    F2 nysK = f2pack(NYS0_F, NYS0_F);   // Kinv*(-sigy - H*alpha)

    const float2* xq = (const float2*)(x + (size_t)b * (T_STEPS * 3));
    float*        opc = out + (size_t)b * (T_STEPS * 3) + comp;

    // J2 update + fc2 partials (NO reduction here — partials returned)
    auto math = [&](float ex, float ey, float eg, float& r0, float& r1, float& r2) {
        const F2 ex2 = f2pack(ex, ex);
        const F2 ey2 = f2pack(ey, ey);
        const F2 eg2 = f2pack(eg, eg);

        // fc1: per-point strain (row 2 pre-scaled by 0.5)
        const F2 e0 = f2fma(ex2, w1p[0][0], f2fma(ey2, w1p[0][1], f2mul(eg2, w1p[0][2])));
        const F2 e1 = f2fma(ex2, w1p[1][0], f2fma(ey2, w1p[1][1], f2mul(eg2, w1p[1][2])));
        const F2 e2 = f2fma(ex2, w1p[2][0], f2fma(ey2, w1p[2][1], f2mul(eg2, w1p[2][2])));

        // elastic predictor, deviatoric form (state negated)
        const F2 eexx = f2add(e0, npxx);
        const F2 eeyy = f2add(e1, npyy);
        const F2 eexy = f2add(e2, npxy);
        const F2 t01  = f2add(e0, e1);
        const F2 pm   = f2mul(K32,  t01);
        const F2 nctr = f2mul(NC232, t01);
        const F2 dxx  = f2fma(TWOMU2, eexx, nctr);
        const F2 dyy  = f2fma(TWOMU2, eeyy, nctr);
        const F2 sxy  = f2mul(TWOMU2, eexy);

        // u = dxx^2 + dxx*dyy + dyy^2 + sxy^2 (q^2 = 3u); TINY seed guards u=0
        const F2 sd  = f2add(dxx, dyy);
        const F2 A   = f2fma(sxy, sxy, TINY2);
        const F2 p1  = f2mul(dxx, sd);
        const F2 p2  = f2fma(dyy, dyy, A);
        const F2 u2  = f2add(p1, p2);

        // radial return (sqrt(3), Kinv folded); only rsqrt is scalar
        float u_lo, u_hi;
        f2unpack(u2, u_lo, u_hi);
        const F2 r2p = f2pack(rsqrtf(u_lo), rsqrtf(u_hi));
        const F2 nr2 = f2mul(N15S32, r2p);
        const F2 ur2 = f2mul(u2, r2p);             // sqrt(u) = q/sqrt(3)
        const F2 fk2 = f2fma(KS32, ur2, nysK);     // Kinv*(q - sigy - H*alpha)
        const F2 dg2 = f2relu(fk2);
        nysK = f2fma(NHK2, dg2, nysK);
        const F2 nc2 = f2mul(dg2, nr2);            // -1.5*dgam/q

        // commit plastic strain
        npxx = f2fma(nc2, dxx, npxx);
        npyy = f2fma(nc2, dyy, npyy);
        npxy = f2fma(nc2, sxy, npxy);

        // corrected stress: o = d*(1 + 2mu*nc) + pm
        const F2 wf  = f2fma(TWOMU2, nc2, ONE2);
        const F2 oxx = f2fma(dxx, wf, pm);
        const F2 oyy = f2fma(dyy, wf, pm);
        const F2 oxy = f2mul(sxy, wf);

        // fc2 partial (softplus weights)
        const F2 a0 = f2fma(oxx, w2p[0][0], f2fma(oyy, w2p[0][1], f2mul(oxy, w2p[0][2])));
        const F2 a1 = f2fma(oxx, w2p[1][0], f2fma(oyy, w2p[1][1], f2mul(oxy, w2p[1][2])));
        const F2 a2 = f2fma(oxx, w2p[2][0], f2fma(oyy, w2p[2][1], f2mul(oxy, w2p[2][2])));

        float a0l, a0h, a1l, a1h, a2l, a2h;
        f2unpack(a0, a0l, a0h);
        f2unpack(a1, a1l, a1h);
        f2unpack(a2, a2l, a2h);
        r0 = a0l + a0h; r1 = a1l + a1h; r2 = a2l + a2h;
    };

    // lagged transpose-reduction + store (4 SHFL); runs one step behind math
    auto reduce_store = [&](float r0, float r1, float r2, int t, bool en) {
        float v1 = lo4 ? r2 : r0;
        float w1 = __shfl_xor_sync(0xffffffffu, v1, 4);
        if (lo4) r0 += w1; else r2 += w1;
        float w2 = __shfl_xor_sync(0xffffffffu, r1, 4);
        if (lo4) r1 += w2;
        float v3 = lo4 ? (r2sel ? r0 : r1) : r2;
        float w3 = __shfl_xor_sync(0xffffffffu, v3, 2);
        if (lo2)      r0 += w3;
        else if (mid) r1 += w3;
        else          r2 += w3;
        float v4 = lo2 ? r0 : (lo4 ? r1 : r2);
        float w4 = __shfl_xor_sync(0xffffffffu, v4, 1);
        const float total = v4 + w4;
        if (do_store && en) opc[3 * t] = total;
    };

    // software-pipelined pair loads (3 x LDG.64 per 2 steps)
    float2 cA = xq[0], cB = xq[1], cC = xq[2];
    float p0 = 0.f, p1 = 0.f, p2 = 0.f;   // partials of step 2k-1 (lagged)

    #pragma unroll 1
    for (int k = 0; k < T_STEPS / 2; ++k) {
        // clamped prefetch of the next pair (no branch)
        const float2* nq = xq + ((k + 1 < T_STEPS / 2) ? 3 : 0);
        const float2 nA = nq[0], nB = nq[1], nC = nq[2];

        float c00, c01, c02, c10, c11, c12;
        // math(2k) issues first; reduction of step 2k-1 overlaps it
        math(cA.x, cA.y, cB.x, c00, c01, c02);
        reduce_store(p0, p1, p2, 2 * k - 1, k > 0);
        // math(2k+1) issues; reduction of step 2k overlaps it
        math(cB.y, cC.x, cC.y, c10, c11, c12);
        reduce_store(c00, c01, c02, 2 * k, true);

        p0 = c10; p1 = c11; p2 = c12;
        cA = nA; cB = nB; cC = nC;
        xq += 3;
    }
    // drain: final step's reduction
    reduce_store(p0, p1, p2, T_STEPS - 1, true);
}

extern "C" void kernel_launch(void* const* d_in, const int* in_sizes, int n_in,
                              void* d_out, int out_size)
{
    const float* x  = (const float*)d_in[0];   // [B, T, 3]
    const float* W1 = (const float*)d_in[1];   // [48, 3]
    const float* W2 = (const float*)d_in[2];   // [3, 48]
    float* out      = (float*)d_out;           // [B, T, 3]

    const int B = in_sizes[0] / (T_STEPS * 3);
    const int total_threads = B * TPB;
    const int grid = (total_threads + BLOCK - 1) / BLOCK;

    prnn_j2_kernel<<<grid, BLOCK>>>(x, W1, W2, out, B);
}